// round 3
// baseline (speedup 1.0000x reference)
#include <cuda_runtime.h>

#define A_COEF 0.01f
#define B_COEF 4.81f
#define C_COEF 0.0f
#define OOB_COST 3.0f

#define ROWS_PER_THREAD 16

__device__ __forceinline__ float penal(float v) {
    float cost = C_COEF + A_COEF * __expf(B_COEF * (1.0f + v));
    bool in_bounds = (v >= 0.0f) && (v <= 1.0f);
    return in_bounds ? cost : OOB_COST;
}

__global__ void __launch_bounds__(256) penalizer_kernel(
    const float* __restrict__ X, float* __restrict__ out, int n_rows)
{
    int t = blockIdx.x * blockDim.x + threadIdx.x;
    long long base = (long long)t * ROWS_PER_THREAD;

    if (base + ROWS_PER_THREAD - 1 < n_rows) {
        // 16 independent streaming loads, front-batched for max MLP.
        float v[ROWS_PER_THREAD];
        #pragma unroll
        for (int i = 0; i < ROWS_PER_THREAD; ++i) {
            v[i] = __ldcs(X + (base + i) * 8 + 7);
        }
        float4* o4 = reinterpret_cast<float4*>(out) + (long long)t * (ROWS_PER_THREAD / 4);
        #pragma unroll
        for (int j = 0; j < ROWS_PER_THREAD / 4; ++j) {
            float4 r;
            r.x = penal(v[j * 4 + 0]);
            r.y = penal(v[j * 4 + 1]);
            r.z = penal(v[j * 4 + 2]);
            r.w = penal(v[j * 4 + 3]);
            __stcs(o4 + j, r);
        }
    } else {
        // tail (not hit when N % 16 == 0, but stay correct generally)
        for (long long i = base; i < n_rows; ++i) {
            out[i] = penal(__ldcs(X + i * 8 + 7));
        }
    }
}

extern "C" void kernel_launch(void* const* d_in, const int* in_sizes, int n_in,
                              void* d_out, int out_size)
{
    const float* X = (const float*)d_in[0];
    float* out = (float*)d_out;
    int n_rows = in_sizes[0] / 8;          // [N, 8] fp32
    int n_threads = (n_rows + ROWS_PER_THREAD - 1) / ROWS_PER_THREAD;
    int block = 256;
    int grid = (n_threads + block - 1) / block;
    penalizer_kernel<<<grid, block>>>(X, out, n_rows);
}

// round 4
// speedup vs baseline: 1.1085x; 1.1085x over previous
#include <cuda_runtime.h>

#define A_COEF 0.01f
#define B_COEF 4.81f
#define C_COEF 0.0f
#define OOB_COST 3.0f

#define ROWS_PER_THREAD 8
#define BLOCK 256

__device__ __forceinline__ float penal(float v) {
    float cost = C_COEF + A_COEF * __expf(B_COEF * (1.0f + v));
    bool in_bounds = (v >= 0.0f) && (v <= 1.0f);
    return in_bounds ? cost : OOB_COST;
}

__global__ void __launch_bounds__(BLOCK) penalizer_kernel(
    const float* __restrict__ X, float* __restrict__ out, int n_rows)
{
    // Block-interleaved: iteration j, the warp's 32 lanes read 32 CONSECUTIVE
    // rows (1024B contiguous) -> only 8 x 128B lines per warp-LDG instead of 32.
    long long blockBase = (long long)blockIdx.x * (BLOCK * ROWS_PER_THREAD);

    if (blockBase + BLOCK * ROWS_PER_THREAD <= n_rows) {
        float v[ROWS_PER_THREAD];
        #pragma unroll
        for (int j = 0; j < ROWS_PER_THREAD; ++j) {
            long long row = blockBase + j * BLOCK + threadIdx.x;
            v[j] = __ldcs(X + row * 8 + 7);
        }
        #pragma unroll
        for (int j = 0; j < ROWS_PER_THREAD; ++j) {
            long long row = blockBase + j * BLOCK + threadIdx.x;
            __stcs(out + row, penal(v[j]));
        }
    } else {
        // tail block (not hit when n_rows % (BLOCK*ROWS_PER_THREAD) == 0)
        for (int j = 0; j < ROWS_PER_THREAD; ++j) {
            long long row = blockBase + j * BLOCK + threadIdx.x;
            if (row < n_rows) {
                out[row] = penal(__ldcs(X + row * 8 + 7));
            }
        }
    }
}

extern "C" void kernel_launch(void* const* d_in, const int* in_sizes, int n_in,
                              void* d_out, int out_size)
{
    const float* X = (const float*)d_in[0];
    float* out = (float*)d_out;
    int n_rows = in_sizes[0] / 8;          // [N, 8] fp32
    long long rows_per_block = (long long)BLOCK * ROWS_PER_THREAD;
    int grid = (int)((n_rows + rows_per_block - 1) / rows_per_block);
    penalizer_kernel<<<grid, BLOCK>>>(X, out, n_rows);
}

// round 5
// speedup vs baseline: 1.1117x; 1.0029x over previous
#include <cuda_runtime.h>

#define A_COEF 0.01f
#define B_COEF 4.81f
#define C_COEF 0.0f
#define OOB_COST 3.0f

#define ROWS_PER_THREAD 16
#define BLOCK 256

__device__ __forceinline__ float penal(float v) {
    float cost = C_COEF + A_COEF * __expf(B_COEF * (1.0f + v));
    bool in_bounds = (v >= 0.0f) && (v <= 1.0f);
    return in_bounds ? cost : OOB_COST;
}

__global__ void __launch_bounds__(BLOCK) penalizer_kernel(
    const float* __restrict__ X, float* __restrict__ out, int n_rows)
{
    // Block-interleaved: each iteration j, a warp's 32 lanes read 32 CONSECUTIVE
    // rows (1024B contiguous) -> 8 x 128B lines per warp-LDG. 16 front-batched
    // loads per thread for deep MLP.
    long long blockBase = (long long)blockIdx.x * (BLOCK * ROWS_PER_THREAD);

    if (blockBase + BLOCK * ROWS_PER_THREAD <= n_rows) {
        float v[ROWS_PER_THREAD];
        #pragma unroll
        for (int j = 0; j < ROWS_PER_THREAD; ++j) {
            long long row = blockBase + j * BLOCK + threadIdx.x;
            v[j] = __ldcs(X + row * 8 + 7);
        }
        #pragma unroll
        for (int j = 0; j < ROWS_PER_THREAD; ++j) {
            long long row = blockBase + j * BLOCK + threadIdx.x;
            __stcs(out + row, penal(v[j]));
        }
    } else {
        // tail block (not hit when n_rows % (BLOCK*ROWS_PER_THREAD) == 0)
        for (int j = 0; j < ROWS_PER_THREAD; ++j) {
            long long row = blockBase + j * BLOCK + threadIdx.x;
            if (row < n_rows) {
                out[row] = penal(__ldcs(X + row * 8 + 7));
            }
        }
    }
}

extern "C" void kernel_launch(void* const* d_in, const int* in_sizes, int n_in,
                              void* d_out, int out_size)
{
    const float* X = (const float*)d_in[0];
    float* out = (float*)d_out;
    int n_rows = in_sizes[0] / 8;          // [N, 8] fp32
    long long rows_per_block = (long long)BLOCK * ROWS_PER_THREAD;
    int grid = (int)((n_rows + rows_per_block - 1) / rows_per_block);
    penalizer_kernel<<<grid, BLOCK>>>(X, out, n_rows);
}